// round 2
// baseline (speedup 1.0000x reference)
#include <cuda_runtime.h>

#define BB 128
#define TT 1024
#define VV 192
#define NTHREADS 384
#define HALF 96
#define NWARPS 12

__global__ __launch_bounds__(NTHREADS, 1)
void crf_loss_kernel(const float* __restrict__ em,
                     const int* __restrict__ tags,
                     const int* __restrict__ mask,
                     const float* __restrict__ trans,
                     const float* __restrict__ start_t,
                     const float* __restrict__ end_t,
                     float* __restrict__ out)
{
    __shared__ __align__(16) float s_p[VV];      // exp(alpha - m), broadcast source
    __shared__ float s_partial[VV];              // half-1 partial sums / final sum scratch
    __shared__ float s_wred[NWARPS];             // per-warp reduction scratch (float)
    __shared__ int   s_ired[NWARPS];             // per-warp reduction scratch (int)
    __shared__ float s_num;                      // gold score
    __shared__ float s_seqlen;

    const int b    = blockIdx.x;
    const int tid  = threadIdx.x;
    const int lane = tid & 31;
    const int wid  = tid >> 5;
    const int h    = tid / VV;      // 0 or 1: which K-half this thread owns
    const int j    = tid - h * VV;  // output column

    const float* emB = em   + (size_t)b * TT * VV;
    const int*   tgB = tags + (size_t)b * TT;
    const int*   mkB = mask + (size_t)b * TT;

    // ---------------- expT half-column into registers ----------------
    float col[HALF];
    #pragma unroll
    for (int i = 0; i < HALF; i++) {
        col[i] = __expf(trans[(h * HALF + i) * VV + j]);
    }

    // ---------------- gold score + mask sum (numerator) ----------------
    float gsum = 0.f;
    int   msum = 0;
    for (int t = tid; t < TT; t += NTHREADS) {
        int mk = mkB[t];
        msum += mk;
        if (t >= 1 && mk) {
            int tg = tgB[t];
            int tp = tgB[t - 1];
            gsum += emB[t * VV + tg] + trans[tp * VV + tg];
        }
    }
    #pragma unroll
    for (int o = 16; o > 0; o >>= 1) {
        gsum += __shfl_xor_sync(0xffffffffu, gsum, o);
        msum += __shfl_xor_sync(0xffffffffu, msum, o);
    }
    if (lane == 0) { s_wred[wid] = gsum; s_ired[wid] = msum; }
    __syncthreads();
    if (tid == 0) {
        float g = 0.f; int mtot = 0;
        #pragma unroll
        for (int w = 0; w < NWARPS; w++) { g += s_wred[w]; mtot += s_ired[w]; }
        int tag0  = tgB[0];
        float num = start_t[tag0] + emB[tag0] + g;
        int last  = mtot - 1; if (last < 0) last = 0;
        num += end_t[tgB[last]];
        s_num    = num;
        s_seqlen = fmaxf((float)mtot, 1.0f);
    }
    __syncthreads();

    // ---------------- forward recursion (log partition) ----------------
    float alpha = 0.f;
    if (tid < VV) alpha = start_t[j] + emB[j];

    float emit_next = 0.f;
    if (tid < VV) emit_next = emB[VV + j];   // t = 1 emission

    for (int t = 1; t < TT; t++) {
        const float emit_cur = emit_next;
        const int   mk = mkB[t];
        // prefetch next step's emission (clamped)
        {
            int tn = (t + 1 < TT) ? (t + 1) : (TT - 1);
            if (tid < VV) emit_next = emB[tn * VV + j];
        }

        // block max of alpha over the 192 owner threads (warps 0..5)
        float wm = alpha;
        #pragma unroll
        for (int o = 16; o > 0; o >>= 1)
            wm = fmaxf(wm, __shfl_xor_sync(0xffffffffu, wm, o));
        if (tid < VV && lane == 0) s_wred[wid] = wm;
        __syncthreads();                                   // S1
        float m = s_wred[0];
        #pragma unroll
        for (int w = 1; w < 6; w++) m = fmaxf(m, s_wred[w]);

        if (tid < VV) s_p[j] = __expf(alpha - m);
        __syncthreads();                                   // S2

        // mat-vec partial: this thread's 96-element half-column
        const float4* p4 = (const float4*)(s_p + h * HALF);
        float a0 = 0.f, a1 = 0.f, a2 = 0.f, a3 = 0.f;
        #pragma unroll
        for (int q = 0; q < HALF / 4; q++) {
            float4 pv = p4[q];
            a0 = fmaf(pv.x, col[4 * q + 0], a0);
            a1 = fmaf(pv.y, col[4 * q + 1], a1);
            a2 = fmaf(pv.z, col[4 * q + 2], a2);
            a3 = fmaf(pv.w, col[4 * q + 3], a3);
        }
        float part = (a0 + a1) + (a2 + a3);
        if (h == 1) s_partial[j] = part;
        __syncthreads();                                   // S3

        if (tid < VV) {
            float s  = part + s_partial[j];
            float na = m + __logf(s) + emit_cur;
            alpha = mk ? na : alpha;
        }
    }

    // ---------------- final lse(alpha + end_trans) ----------------
    float v = (tid < VV) ? (alpha + end_t[j]) : -3.0e38f;
    float wm2 = v;
    #pragma unroll
    for (int o = 16; o > 0; o >>= 1)
        wm2 = fmaxf(wm2, __shfl_xor_sync(0xffffffffu, wm2, o));
    if (lane == 0) s_wred[wid] = wm2;
    __syncthreads();                                       // F1
    float m2 = s_wred[0];
    #pragma unroll
    for (int w = 1; w < NWARPS; w++) m2 = fmaxf(m2, s_wred[w]);

    float e = (tid < VV) ? __expf(v - m2) : 0.f;
    #pragma unroll
    for (int o = 16; o > 0; o >>= 1)
        e += __shfl_xor_sync(0xffffffffu, e, o);
    if (lane == 0) s_partial[wid] = e;
    __syncthreads();                                       // F2

    if (tid == 0) {
        float ssum = 0.f;
        #pragma unroll
        for (int w = 0; w < NWARPS; w++) ssum += s_partial[w];
        float logden = m2 + logf(ssum + 1e-8f);
        out[b] = (logden - s_num) / s_seqlen;
    }
}

extern "C" void kernel_launch(void* const* d_in, const int* in_sizes, int n_in,
                              void* d_out, int out_size)
{
    const float* em    = (const float*)d_in[0];
    const int*   tags  = (const int*)d_in[1];
    const int*   mask  = (const int*)d_in[2];
    const float* trans = (const float*)d_in[3];
    const float* st    = (const float*)d_in[4];
    const float* en    = (const float*)d_in[5];
    float* out = (float*)d_out;

    crf_loss_kernel<<<BB, NTHREADS>>>(em, tags, mask, trans, st, en, out);
}